// round 7
// baseline (speedup 1.0000x reference)
#include <cuda_runtime.h>
#include <cuda_bf16.h>
#include <math.h>
#include <stdint.h>

#define BATCH 8
#define WIN   4096
#define RDIM  128
#define DDIM  128
#define BLKSZ 128
#define NBLK  (WIN / BLKSZ)   // 32
#define NTILE (BATCH * NBLK)  // 256

// ---------------- scratch (device globals) ----------------------------------
__device__ float g_pow[(BLKSZ + 1) * RDIM];   // pow[n][r] = gamma_r^n
__device__ float g_ipow[BLKSZ * RDIM];        // ipow[n][r] = gamma_r^{-n}
__device__ float g_S[NTILE * RDIM * DDIM];
// state pre-split by scan_kernel: bf16 hi/lo pairs, [tile][r][64 dpair words]
__device__ __align__(256) uint32_t g_state_hi[NTILE * RDIM * (DDIM / 2)];
__device__ __align__(256) uint32_t g_state_lo[NTILE * RDIM * (DDIM / 2)];

// inverse-causal build share boundaries (weights 8..1 over 8192 items)
__constant__ int c_bstart[9] = {0, 1820, 3413, 4779, 5916, 6827, 7509, 7964, 8192};

// ---------------- smem layout ------------------------------------------------
// M: split bf16 matrix (hi half then lo half), rows padded to 68 words.
#define SROW_W 68
#define ROWB   (SROW_W * 4)          // 272 B
#define HALF_W (128 * SROW_W)
#define HALF_B (HALF_W * 4)          // 34816 B
#define MAT_W  (2 * HALF_W)
#define MAT_B  (MAT_W * 4)           // 69632 B
#define PF_B   HALF_B                // 34816 B prefetch region
#define O_SMEM (MAT_B + PF_B)        // 104448 B -> 2 CTAs/SM
#define S_SMEM MAT_B

// ---------------- helpers ----------------------------------------------------
__device__ __forceinline__ uint32_t pkbf(float a, float b) {
    __nv_bfloat162 t = __floats2bfloat162_rn(a, b);
    return *reinterpret_cast<uint32_t*>(&t);
}
__device__ __forceinline__ void split1(float v, float& hi, float& lo) {
    __nv_bfloat16 h = __float2bfloat16(v);
    hi = __bfloat162float(h);
    lo = v - hi;
}
__device__ __forceinline__ void split2(float a, float b, uint32_t& ph, uint32_t& pl) {
    float h0, l0, h1, l1;
    split1(a, h0, l0);
    split1(b, h1, l1);
    ph = pkbf(h0, h1);
    pl = pkbf(l0, l1);
}
__device__ __forceinline__ void mma_bf16(float* c, const uint32_t* a, const uint32_t* b) {
    asm volatile(
        "mma.sync.aligned.m16n8k16.row.col.f32.bf16.bf16.f32 "
        "{%0,%1,%2,%3}, {%4,%5,%6,%7}, {%8,%9}, {%0,%1,%2,%3};"
        : "+f"(c[0]), "+f"(c[1]), "+f"(c[2]), "+f"(c[3])
        : "r"(a[0]), "r"(a[1]), "r"(a[2]), "r"(a[3]), "r"(b[0]), "r"(b[1]));
}
__device__ __forceinline__ void ldsm_x4(uint32_t* r, uint32_t a) {
    asm volatile("ldmatrix.sync.aligned.m8n8.x4.shared.b16 {%0,%1,%2,%3}, [%4];"
        : "=r"(r[0]), "=r"(r[1]), "=r"(r[2]), "=r"(r[3]) : "r"(a));
}
__device__ __forceinline__ void ldsm_x4_t(uint32_t* r, uint32_t a) {
    asm volatile("ldmatrix.sync.aligned.m8n8.x4.trans.shared.b16 {%0,%1,%2,%3}, [%4];"
        : "=r"(r[0]), "=r"(r[1]), "=r"(r[2]), "=r"(r[3]) : "r"(a));
}
__device__ __forceinline__ void cpasync16(uint32_t dst, const void* src) {
    asm volatile("cp.async.cg.shared.global [%0], [%1], 16;"
                 :: "r"(dst), "l"(src) : "memory");
}
#define CP_COMMIT() asm volatile("cp.async.commit_group;" ::: "memory")
#define CP_WAIT(n)  asm volatile("cp.async.wait_group %0;" :: "n"(n) : "memory")

// A fragment streamed from global, natural layout: A[i][r] = src[i][r]*scl[i][r]
__device__ __forceinline__ void ldA_nat(uint32_t* ah, uint32_t* al,
                                        const float* base, const float* sclb,
                                        int kt, int lane) {
    int g = lane >> 2, tc = lane & 3;
    int c = kt * 16 + tc * 2;
    const float* p = base + g * 128 + c;
    const float* w = sclb + g * 128 + c;
    float2 v0 = *(const float2*)(p);
    float2 s0 = *(const float2*)(w);
    float2 v1 = *(const float2*)(p + 8);
    float2 s1 = *(const float2*)(w + 8);
    float2 v2 = *(const float2*)(p + 8 * 128);
    float2 s2 = *(const float2*)(w + 8 * 128);
    float2 v3 = *(const float2*)(p + 8 * 128 + 8);
    float2 s3 = *(const float2*)(w + 8 * 128 + 8);
    split2(v0.x * s0.x, v0.y * s0.y, ah[0], al[0]);
    split2(v2.x * s2.x, v2.y * s2.y, ah[1], al[1]);
    split2(v1.x * s1.x, v1.y * s1.y, ah[2], al[2]);
    split2(v3.x * s3.x, v3.y * s3.y, ah[3], al[3]);
}
// hi-only variant (GEMM3 pass2)
__device__ __forceinline__ void ldA_hi(uint32_t* ah,
                                       const float* base, const float* sclb,
                                       int kt, int lane) {
    int g = lane >> 2, tc = lane & 3;
    int c = kt * 16 + tc * 2;
    const float* p = base + g * 128 + c;
    const float* w = sclb + g * 128 + c;
    float2 v0 = *(const float2*)(p);
    float2 s0 = *(const float2*)(w);
    float2 v1 = *(const float2*)(p + 8);
    float2 s1 = *(const float2*)(w + 8);
    float2 v2 = *(const float2*)(p + 8 * 128);
    float2 s2 = *(const float2*)(w + 8 * 128);
    float2 v3 = *(const float2*)(p + 8 * 128 + 8);
    float2 s3 = *(const float2*)(w + 8 * 128 + 8);
    ah[0] = pkbf(v0.x * s0.x, v0.y * s0.y);
    ah[1] = pkbf(v2.x * s2.x, v2.y * s2.y);
    ah[2] = pkbf(v1.x * s1.x, v1.y * s1.y);
    ah[3] = pkbf(v3.x * s3.x, v3.y * s3.y);
}

// A fragment streamed transposed+scaled (s_kernel): A[r][j] = k[j][r]*g^{127-j}
__device__ __forceinline__ float ktr_elem(const float* kb, int j, int r) {
    return kb[j * 128 + r] * g_pow[(127 - j) * 128 + r];
}
__device__ __forceinline__ void ldA_ktr(uint32_t* ah, uint32_t* al,
                                        const float* kb, int mrow, int kt, int lane) {
    int g = lane >> 2, tc = lane & 3;
    int r = mrow + g;
    int j = kt * 16 + tc * 2;
    split2(ktr_elem(kb, j,     r),     ktr_elem(kb, j + 1, r),     ah[0], al[0]);
    split2(ktr_elem(kb, j,     r + 8), ktr_elem(kb, j + 1, r + 8), ah[1], al[1]);
    split2(ktr_elem(kb, j + 8, r),     ktr_elem(kb, j + 9, r),     ah[2], al[2]);
    split2(ktr_elem(kb, j + 8, r + 8), ktr_elem(kb, j + 9, r + 8), ah[3], al[3]);
}

// scale+split+store, natural layout, uniform shares
__device__ __forceinline__ void build_scaled(const float* __restrict__ src,
                                             const float* __restrict__ scl,
                                             uint32_t* __restrict__ mat, int tid) {
#pragma unroll 4
    for (int p = tid; p < 8192; p += 256) {
        int i = p >> 6, cp = p & 63;
        float2 v = *reinterpret_cast<const float2*>(src + i * 128 + cp * 2);
        float2 s = *reinterpret_cast<const float2*>(scl + i * 128 + cp * 2);
        uint32_t ph, pl;
        split2(v.x * s.x, v.y * s.y, ph, pl);
        int w = i * SROW_W + cp;
        mat[w] = ph;
        mat[w + HALF_W] = pl;
    }
}
// copy+split+store, natural layout, uniform shares (s_kernel)
__device__ __forceinline__ void build_copy(const float* __restrict__ src,
                                           uint32_t* __restrict__ mat, int tid) {
#pragma unroll 4
    for (int p = tid; p < 8192; p += 256) {
        int i = p >> 6, cp = p & 63;
        float2 v = *reinterpret_cast<const float2*>(src + i * 128 + cp * 2);
        uint32_t ph, pl;
        split2(v.x, v.y, ph, pl);
        int w = i * SROW_W + cp;
        mat[w] = ph;
        mat[w + HALF_W] = pl;
    }
}

// ---------------- kernel 0: decay power tables ------------------------------
__global__ void pow_kernel(const float* __restrict__ gamma) {
    int n = blockIdx.x;
    int r = threadIdx.x;
    float g = fmaxf(gamma[r], 1e-8f);
    float lg = logf(g);
    g_pow[n * RDIM + r] = expf((float)n * lg);
    if (n < BLKSZ) g_ipow[n * RDIM + r] = expf(-(float)n * lg);
}

// ---------------- kernel 1: S[r,d] = sum_j gamma^{127-j} k[j,r] h[j,d] ------
__global__ __launch_bounds__(256, 2)
void s_kernel(const float* __restrict__ k, const float* __restrict__ h) {
    extern __shared__ uint32_t smw[];
    uint32_t* M = smw;

    int tid = threadIdx.x;
    int lane = tid & 31, wid = tid >> 5;
    int wrow = wid * 16;
    int bn = blockIdx.x;
    int b = bn / NBLK, n = bn % NBLK;
    const float* kp = k + ((size_t)b * WIN + (size_t)n * BLKSZ) * RDIM;
    const float* hp = h + ((size_t)b * WIN + (size_t)n * BLKSZ) * DDIM;
    float* Sp = g_S + (size_t)bn * RDIM * DDIM;

    build_copy(hp, M, tid);
    __syncthreads();

    uint32_t sb = (uint32_t)__cvta_generic_to_shared(M);
    int lrow = lane & 7, seg = lane >> 3;
    uint32_t off_t = (uint32_t)((((seg & 1) << 3) + lrow) * ROWB + (((seg >> 1) << 3) << 1));

    float C[16][4];
#pragma unroll
    for (int nt = 0; nt < 16; nt++)
#pragma unroll
        for (int v = 0; v < 4; v++) C[nt][v] = 0.f;

#pragma unroll 2
    for (int kt = 0; kt < 8; kt++) {
        uint32_t ah[4], al[4];
        ldA_ktr(ah, al, kp, wrow, kt, lane);
        uint32_t kb = sb + (uint32_t)(kt * 16) * ROWB + off_t;
#pragma unroll
        for (int p = 0; p < 8; p++) {
            uint32_t bh[4], bl[4];
            ldsm_x4_t(bh, kb + p * 32);
            ldsm_x4_t(bl, kb + p * 32 + HALF_B);
            mma_bf16(C[2 * p],     ah, bh);
            mma_bf16(C[2 * p],     ah, bl);
            mma_bf16(C[2 * p],     al, bh);
            mma_bf16(C[2 * p + 1], ah, bh + 2);
            mma_bf16(C[2 * p + 1], ah, bl + 2);
            mma_bf16(C[2 * p + 1], al, bh + 2);
        }
    }

    int g = lane >> 2, tc = lane & 3;
#pragma unroll
    for (int nt = 0; nt < 16; nt++) {
        int d0 = nt * 8 + tc * 2;
        *reinterpret_cast<float2*>(Sp + (wrow + g) * 128 + d0) =
            make_float2(C[nt][0], C[nt][1]);
        *reinterpret_cast<float2*>(Sp + (wrow + g + 8) * 128 + d0) =
            make_float2(C[nt][2], C[nt][3]);
    }
}

// ---------------- kernel 2: scan over blocks; emits pre-split state ---------
// block (32,8): x = d-quad, y = r-sub; grid (16, BATCH)
__global__ void scan_kernel() {
    int dq = threadIdx.x;
    int r = blockIdx.x * 8 + threadIdx.y;
    int b = blockIdx.y;
    float g = g_pow[BLKSZ * RDIM + r];
    float4 s = make_float4(0.f, 0.f, 0.f, 0.f);
    for (int n = 0; n < NBLK; n++) {
        size_t tile = (size_t)b * NBLK + n;
        size_t widx = (tile * RDIM + r) * (DDIM / 2) + dq * 2;
        uint32_t h0, l0, h1, l1;
        split2(s.x, s.y, h0, l0);
        split2(s.z, s.w, h1, l1);
        *reinterpret_cast<uint2*>(&g_state_hi[widx]) = make_uint2(h0, h1);
        *reinterpret_cast<uint2*>(&g_state_lo[widx]) = make_uint2(l0, l1);
        float4 Sv = *reinterpret_cast<const float4*>(
            &g_S[(tile * RDIM + r) * DDIM + dq * 4]);
        s.x = fmaf(g, s.x, Sv.x);
        s.y = fmaf(g, s.y, Sv.y);
        s.z = fmaf(g, s.z, Sv.z);
        s.w = fmaf(g, s.w, Sv.w);
    }
}

// ---------------- kernel 3: per-tile output ---------------------------------
__global__ __launch_bounds__(256, 2)
void out_kernel(const float* __restrict__ q, const float* __restrict__ kk,
                const float* __restrict__ h, float* __restrict__ out) {
    extern __shared__ uint32_t smw[];
    uint32_t* M = smw;                         // Khat -> H -> state-lo
    float* PFf = (float*)(smw + MAT_W);        // raw H rows 0-63, then state-hi

    int tid = threadIdx.x;
    int lane = tid & 31, wid = tid >> 5;
    int wrow = wid * 16;
    int g = lane >> 2, tc = lane & 3;
    int bn = blockIdx.x;
    int b = bn / NBLK, n = bn % NBLK;
    const float* qp = q  + ((size_t)b * WIN + (size_t)n * BLKSZ) * RDIM;
    const float* kp = kk + ((size_t)b * WIN + (size_t)n * BLKSZ) * RDIM;
    const float* hp = h  + ((size_t)b * WIN + (size_t)n * BLKSZ) * DDIM;
    float* op = out + ((size_t)b * WIN + (size_t)n * BLKSZ) * DDIM;

    const float* qwp = qp + wrow * 128;
    const float* pw0 = g_pow + wrow * RDIM;
    const float* pw1 = g_pow + (wrow + 1) * RDIM;

    uint32_t sb = (uint32_t)__cvta_generic_to_shared(M);
    uint32_t pfb = sb + MAT_B;
    int lrow = lane & 7, seg = lane >> 3;
    uint32_t off_n = (uint32_t)(((lrow + ((seg >> 1) << 3)) * ROWB) + ((seg & 1) << 4));
    uint32_t off_t = (uint32_t)((((seg & 1) << 3) + lrow) * ROWB + (((seg >> 1) << 3) << 1));

    // ---- prefetch raw H rows 0-63 into PF (lands under build+GEMM1) -------
#pragma unroll
    for (int t = 0; t < 8; t++) {
        int c = tid + t * 256;            // 16B chunk id, < 2048
        cpasync16(pfb + c * 16, (const char*)hp + c * 16);
    }
    CP_COMMIT();

    // ---- build Khat = k * g^-j, natural [j][r] ----------------------------
    build_scaled(kp, g_ipow, M, tid);
    __syncthreads();

    // ---- GEMM1: P = Qhat @ Khat^T  (A streamed; B non-trans LDSM) ---------
    float PC[64];
    uint32_t* Pu = (uint32_t*)PC;
#pragma unroll
    for (int i = 0; i < 64; i++) PC[i] = 0.f;

#pragma unroll 2
    for (int kt = 0; kt < 8; kt++) {
        uint32_t ah[4], al[4];
        ldA_nat(ah, al, qwp, pw0, kt, lane);
        uint32_t kb = sb + (uint32_t)(kt * 32) + off_n;
#pragma unroll
        for (int p = 0; p < 8; p++) {
            if (p > wid) break;                 // causal
            uint32_t bh[4], bl[4];
            ldsm_x4(bh, kb + (uint32_t)(p * 16) * ROWB);
            ldsm_x4(bl, kb + (uint32_t)(p * 16) * ROWB + HALF_B);
            mma_bf16(PC + 8 * p,     ah, bh);
            mma_bf16(PC + 8 * p,     ah, bl);
            mma_bf16(PC + 8 * p,     al, bh);
            mma_bf16(PC + 8 * p + 4, ah, bh + 2);
            mma_bf16(PC + 8 * p + 4, ah, bl + 2);
            mma_bf16(PC + 8 * p + 4, al, bh + 2);
        }
    }

    // ---- causal mask + split P -> pah/pal IN PLACE ------------------------
    // slot map: Pu[8t+0..3] = pah[t][0..3], Pu[8t+4..7] = pal[t][0..3]
#pragma unroll
    for (int t = 0; t < 8; t++) {
        int i0 = wrow + g, i1 = i0 + 8;
        int jb0 = t * 16 + tc * 2, jb1 = jb0 + 8;
        float c0 = (jb0     <= i0) ? PC[8 * t + 0] : 0.f;
        float c1 = (jb0 + 1 <= i0) ? PC[8 * t + 1] : 0.f;
        float c2 = (jb0     <= i1) ? PC[8 * t + 2] : 0.f;
        float c3 = (jb0 + 1 <= i1) ? PC[8 * t + 3] : 0.f;
        float c4 = (jb1     <= i0) ? PC[8 * t + 4] : 0.f;
        float c5 = (jb1 + 1 <= i0) ? PC[8 * t + 5] : 0.f;
        float c6 = (jb1     <= i1) ? PC[8 * t + 6] : 0.f;
        float c7 = (jb1 + 1 <= i1) ? PC[8 * t + 7] : 0.f;
        split2(c0, c1, Pu[8 * t + 0], Pu[8 * t + 4]);
        split2(c2, c3, Pu[8 * t + 1], Pu[8 * t + 5]);
        split2(c4, c5, Pu[8 * t + 2], Pu[8 * t + 6]);
        split2(c6, c7, Pu[8 * t + 3], Pu[8 * t + 7]);
    }

    CP_WAIT(0);            // H rows 0-63 resident in PF
    __syncthreads();       // all warps done reading Khat from M

    // ---- build H (balanced shares; rows<64 from PF, else global) ----------
    {
        int s0 = c_bstart[wid], s1 = c_bstart[wid + 1];
        for (int p = s0 + lane; p < s1; p += 32) {
            int i = p >> 6, cp = p & 63;
            float2 v = (i < 64)
                ? *reinterpret_cast<const float2*>(PFf + i * 128 + cp * 2)
                : *reinterpret_cast<const float2*>(hp + i * 128 + cp * 2);
            uint32_t ph, pl;
            split2(v.x, v.y, ph, pl);
            int w = i * SROW_W + cp;
            M[w] = ph;
            M[w + HALF_W] = pl;
        }
    }
    __syncthreads();       // H ready; PF free

    // ---- issue state-hi -> PF (lands under GEMM2) -------------------------
#pragma unroll
    for (int t = 0; t < 8; t++) {
        int c = tid + t * 256;             // < 2048
        int row = c >> 4, kk16 = c & 15;
        cpasync16(pfb + row * ROWB + kk16 * 16,
                  (const char*)g_state_hi + (size_t)bn * 32768 + row * 256 + kk16 * 16);
    }
    CP_COMMIT();

    // ---- GEMM2: C = P @ H  (A regs; B trans LDSM); two p-halves -----------
    float C[16][4];
#pragma unroll
    for (int nt = 0; nt < 16; nt++)
#pragma unroll
        for (int v = 0; v < 4; v++) C[nt][v] = 0.f;
#pragma unroll
    for (int ph = 0; ph < 2; ph++) {
#pragma unroll
        for (int kt = 0; kt < 8; kt++) {
            if (kt > wid) break;
            uint32_t kb = sb + (uint32_t)(kt * 16) * ROWB + off_t + (uint32_t)(ph * 128);
            const uint32_t* pa = Pu + 8 * kt;
            const uint32_t* pl_ = Pu + 8 * kt + 4;
#pragma unroll
            for (int pp = 0; pp < 4; pp++) {
                int p = ph * 4 + pp;
                uint32_t bh[4], bl[4];
                ldsm_x4_t(bh, kb + pp * 32);
                ldsm_x4_t(bl, kb + pp * 32 + HALF_B);
                mma_bf16(C[2 * p],     pa,  bh);
                mma_bf16(C[2 * p],     pa,  bl);
                mma_bf16(C[2 * p],     pl_, bh);
                mma_bf16(C[2 * p + 1], pa,  bh + 2);
                mma_bf16(C[2 * p + 1], pa,  bl + 2);
                mma_bf16(C[2 * p + 1], pl_, bh + 2);
            }
        }
    }
    __syncthreads();       // all warps done reading H from M

    // ---- issue state-lo -> M (lands under GEMM3 pass1) --------------------
#pragma unroll
    for (int t = 0; t < 8; t++) {
        int c = tid + t * 256;
        int row = c >> 4, kk16 = c & 15;
        cpasync16(sb + row * ROWB + kk16 * 16,
                  (const char*)g_state_lo + (size_t)bn * 32768 + row * 256 + kk16 * 16);
    }
    CP_COMMIT();
    CP_WAIT(1);            // state-hi done (lo may still be in flight)
    __syncthreads();

    // ---- GEMM3 pass1: C += Ah*Bh + Al*Bh   (B-hi in PF) -------------------
#pragma unroll 2
    for (int kt = 0; kt < 8; kt++) {
        uint32_t ah[4], al[4];
        ldA_nat(ah, al, qwp, pw1, kt, lane);
        uint32_t kb = pfb + (uint32_t)(kt * 16) * ROWB + off_t;
#pragma unroll
        for (int p = 0; p < 8; p++) {
            uint32_t bh[4];
            ldsm_x4_t(bh, kb + p * 32);
            mma_bf16(C[2 * p],     ah, bh);
            mma_bf16(C[2 * p],     al, bh);
            mma_bf16(C[2 * p + 1], ah, bh + 2);
            mma_bf16(C[2 * p + 1], al, bh + 2);
        }
    }
    CP_WAIT(0);            // state-lo resident in M
    __syncthreads();

    // ---- GEMM3 pass2: C += Ah*Bl   (B-lo in M) ----------------------------
#pragma unroll 2
    for (int kt = 0; kt < 8; kt++) {
        uint32_t ah[4];
        ldA_hi(ah, qwp, pw1, kt, lane);
        uint32_t kb = sb + (uint32_t)(kt * 16) * ROWB + off_t;
#pragma unroll
        for (int p = 0; p < 8; p++) {
            uint32_t bl[4];
            ldsm_x4_t(bl, kb + p * 32);
            mma_bf16(C[2 * p],     ah, bl);
            mma_bf16(C[2 * p + 1], ah, bl + 2);
        }
    }

    // ---- store ------------------------------------------------------------
#pragma unroll
    for (int nt = 0; nt < 16; nt++) {
        int d0 = nt * 8 + tc * 2;
        *reinterpret_cast<float2*>(op + (wrow + g) * 128 + d0) =
            make_float2(C[nt][0], C[nt][1]);
        *reinterpret_cast<float2*>(op + (wrow + g + 8) * 128 + d0) =
            make_float2(C[nt][2], C[nt][3]);
    }
}

// ---------------- launch ----------------------------------------------------
extern "C" void kernel_launch(void* const* d_in, const int* in_sizes, int n_in,
                              void* d_out, int out_size) {
    const float* q     = (const float*)d_in[0];
    const float* k     = (const float*)d_in[1];
    const float* h     = (const float*)d_in[2];
    const float* gamma = (const float*)d_in[3];
    float* out = (float*)d_out;

    cudaFuncSetAttribute(s_kernel, cudaFuncAttributeMaxDynamicSharedMemorySize,
                         S_SMEM);
    cudaFuncSetAttribute(out_kernel, cudaFuncAttributeMaxDynamicSharedMemorySize,
                         O_SMEM);

    pow_kernel<<<BLKSZ + 1, RDIM>>>(gamma);
    s_kernel<<<NTILE, 256, S_SMEM>>>(k, h);
    scan_kernel<<<dim3(16, BATCH), dim3(32, 8)>>>();
    out_kernel<<<NTILE, 256, O_SMEM>>>(q, k, h, out);
}